// round 6
// baseline (speedup 1.0000x reference)
#include <cuda_runtime.h>
#include <math.h>
#include <stdint.h>

#define BB 4
#define TT 2048
#define DD 1024
#define HH 16
#define HD 64
#define SCALE_F 0.125f   // 1/sqrt(64)

// Scratch. g_q, g_k, g_o: [B, H, T, hd]. g_v: [B, H, hd, T] (TRANSPOSED).
__device__ float g_q[(size_t)BB * HH * TT * HD];
__device__ float g_k[(size_t)BB * HH * TT * HD];
__device__ float g_v[(size_t)BB * HH * TT * HD];
__device__ float g_o[(size_t)BB * HH * TT * HD];
// Pre-rounded X: [B*T, D]
__device__ float g_x[(size_t)BB * TT * DD];
// W^T scratch: 4 matrices [N=1024][K=1024], tf32-rounded
__device__ float g_wt[(size_t)4 * DD * DD];

__device__ __forceinline__ uint32_t f2tf32(float f) {
    uint32_t r;
    asm("cvt.rna.tf32.f32 %0, %1;" : "=r"(r) : "f"(f));
    return r;
}
__device__ __forceinline__ float rtf32(float f) {
    return __uint_as_float(f2tf32(f));
}

__device__ __forceinline__ void mma_tf32(float* d, const uint32_t* a,
                                         const uint32_t* b) {
    asm volatile(
        "mma.sync.aligned.m16n8k8.row.col.f32.tf32.tf32.f32 "
        "{%0,%1,%2,%3}, {%4,%5,%6,%7}, {%8,%9}, {%0,%1,%2,%3};"
        : "+f"(d[0]), "+f"(d[1]), "+f"(d[2]), "+f"(d[3])
        : "r"(a[0]), "r"(a[1]), "r"(a[2]), "r"(a[3]),
          "r"(b[0]), "r"(b[1]));
}

__device__ __forceinline__ void cpasync16(void* sptr, const void* gptr) {
    uint32_t sa = (uint32_t)__cvta_generic_to_shared(sptr);
    asm volatile("cp.async.ca.shared.global [%0], [%1], 16;"
                 :: "r"(sa), "l"(gptr));
}
#define CP_COMMIT() asm volatile("cp.async.commit_group;" ::: "memory")
#define CP_WAIT1()  asm volatile("cp.async.wait_group 1;" ::: "memory")
#define CP_WAIT0()  asm volatile("cp.async.wait_group 0;" ::: "memory")

// XOR swizzle for 64-col fp32 tiles (attention)
#define SW(row, col) (((row) << 6) + ((col) ^ (((row) & 7) << 2)))

// ---------------------------------------------------------------------------
// Pre-round X to tf32: g_x = rtf32(x)
// ---------------------------------------------------------------------------
__global__ __launch_bounds__(256) void round_x(const float* __restrict__ x)
{
    size_t i = ((size_t)blockIdx.x * 256 + threadIdx.x) * 4;
    float4 v = *(const float4*)&x[i];
    uint4 u;
    u.x = f2tf32(v.x); u.y = f2tf32(v.y);
    u.z = f2tf32(v.z); u.w = f2tf32(v.w);
    *(uint4*)&g_x[i] = u;
}

// ---------------------------------------------------------------------------
// Weight transpose: W [K,N] -> g_wt slice [N,K], tf32-rounded
// ---------------------------------------------------------------------------
__global__ __launch_bounds__(256) void transpose_w(
    const float* __restrict__ Wq, const float* __restrict__ Wk,
    const float* __restrict__ Wv, const float* __restrict__ Wo)
{
    const float* src = (blockIdx.z == 0) ? Wq : (blockIdx.z == 1) ? Wk
                     : (blockIdx.z == 2) ? Wv : Wo;
    float* dst = g_wt + (size_t)blockIdx.z * DD * DD;

    __shared__ float tile[32][33];
    int x = blockIdx.x * 32 + threadIdx.x;  // n
    int y0 = blockIdx.y * 32;               // k base
#pragma unroll
    for (int j = threadIdx.y; j < 32; j += 8)
        tile[j][threadIdx.x] = src[(size_t)(y0 + j) * DD + x];
    __syncthreads();
    int x2 = y0 + threadIdx.x;              // k
    int y2 = blockIdx.x * 32;               // n base
#pragma unroll
    for (int j = threadIdx.y; j < 32; j += 8)
        dst[(size_t)(y2 + j) * DD + x2] = rtf32(tile[threadIdx.x][j]);
}

// ---------------------------------------------------------------------------
// cp.async double-buffered tf32 GEMM: C[128x128] = A @ Wt^T (+bias)
// MODE 0: A = g_x; z=0 -> g_q, z=1 -> g_k, z=2 -> g_v TRANSPOSED [B,H,hd,T]
// MODE 1: A gathered from g_o (pre-rounded by attn), out = d_out [B*T, D]
// 256 threads = 8 warps (2m x 4n), warp tile 64x32. BK=16, 2 stages.
// ---------------------------------------------------------------------------
#define BK2 16
#define AST 20   // floats per smem row (16 data + 4 pad); conflict-free

template <int MODE>
__global__ __launch_bounds__(256) void gemm_tc(
    const float* __restrict__ b0, const float* __restrict__ b1,
    const float* __restrict__ b2, float* __restrict__ OutDirect)
{
    __shared__ float sA[2][128 * AST];
    __shared__ float sB[2][128 * AST];

    int tid = threadIdx.x;
    int wid = tid >> 5;
    int lane = tid & 31;
    int warp_m = wid & 1;
    int warp_n = wid >> 1;
    int r = lane >> 2;
    int c = lane & 3;
    int n0 = blockIdx.x * 128;
    int m0 = blockIdx.y * 128;

    const float* Wt;
    const float* bias;
    float* out;
    const float* Ain;
    int zsel = 0;
    if (MODE == 0) {
        zsel = blockIdx.z;
        Wt = g_wt + (size_t)zsel * DD * DD;
        bias = (zsel == 0) ? b0 : (zsel == 1) ? b1 : b2;
        out = (zsel == 0) ? g_q : (zsel == 1) ? g_k : g_v;
        Ain = g_x;
    } else {
        Wt = g_wt + (size_t)3 * DD * DD;
        bias = b0;
        out = OutDirect;
        Ain = g_o;
    }

    // per-thread load coordinates: 2 chunks of 16B for A, 2 for B
    // idx = tid + i*256 in [0,512): row = idx>>2 (0..127), c4 = idx&3
    auto load_stage = [&](int st, int kt) {
#pragma unroll
        for (int i = 0; i < 2; i++) {
            int idx = tid + i * 256;
            int row = idx >> 2;
            int c4 = idx & 3;
            const float* srcA;
            if (MODE == 0) {
                srcA = Ain + (size_t)(m0 + row) * DD + kt + c4 * 4;
            } else {
                int m = m0 + row;
                int b = m >> 11;
                int t = m & 2047;
                int h = kt >> 6;
                int d0 = (kt & 63) + c4 * 4;
                srcA = Ain + (((size_t)b * HH + h) * TT + t) * HD + d0;
            }
            cpasync16(&sA[st][row * AST + c4 * 4], srcA);
            cpasync16(&sB[st][row * AST + c4 * 4],
                      Wt + (size_t)(n0 + row) * DD + kt + c4 * 4);
        }
        CP_COMMIT();
    };

    float acc[4][4][4];
#pragma unroll
    for (int mt = 0; mt < 4; mt++)
#pragma unroll
        for (int nt = 0; nt < 4; nt++)
#pragma unroll
            for (int i = 0; i < 4; i++) acc[mt][nt][i] = 0.f;

    const int NIT = DD / BK2;   // 64
    load_stage(0, 0);

    for (int it = 0; it < NIT; it++) {
        int nxt = it + 1;
        if (nxt < NIT) {
            load_stage(nxt & 1, nxt * BK2);
            CP_WAIT1();
        } else {
            CP_WAIT0();
        }
        __syncthreads();

        const float* cA = sA[it & 1];
        const float* cB = sB[it & 1];
#pragma unroll
        for (int ks = 0; ks < 2; ks++) {
            int k0 = ks * 8;
            uint32_t af[4][4], bf[4][2];
#pragma unroll
            for (int mt = 0; mt < 4; mt++) {
                const float* base = &cA[(warp_m * 64 + mt * 16 + r) * AST + k0 + c];
                af[mt][0] = __float_as_uint(base[0]);
                af[mt][1] = __float_as_uint(base[8 * AST]);
                af[mt][2] = __float_as_uint(base[4]);
                af[mt][3] = __float_as_uint(base[8 * AST + 4]);
            }
#pragma unroll
            for (int nt = 0; nt < 4; nt++) {
                const float* base = &cB[(warp_n * 32 + nt * 8 + r) * AST + k0 + c];
                bf[nt][0] = __float_as_uint(base[0]);
                bf[nt][1] = __float_as_uint(base[4]);
            }
#pragma unroll
            for (int mt = 0; mt < 4; mt++)
#pragma unroll
                for (int nt = 0; nt < 4; nt++)
                    mma_tf32(acc[mt][nt], af[mt], bf[nt]);
        }
        __syncthreads();
    }

    // ---- epilogue ----
#pragma unroll
    for (int nt = 0; nt < 4; nt++) {
        int col = n0 + warp_n * 32 + nt * 8 + c * 2;
        float bx = __ldg(&bias[col]);
        float by = __ldg(&bias[col + 1]);
#pragma unroll
        for (int mt = 0; mt < 4; mt++) {
            int row0 = m0 + warp_m * 64 + mt * 16 + r;
            float2 v0, v1;
            v0.x = acc[mt][nt][0] + bx;
            v0.y = acc[mt][nt][1] + by;
            v1.x = acc[mt][nt][2] + bx;
            v1.y = acc[mt][nt][3] + by;
            if (MODE == 0) {
                int head = col >> 6;
                int d = col & 63;
                int b = row0 >> 11;
                int t = row0 & 2047;
                if (zsel == 2) {
                    // V transposed: [B,H,hd,T]
                    size_t vb = ((size_t)b * HH + head) * HD;
                    out[(vb + d) * TT + t] = v0.x;
                    out[(vb + d + 1) * TT + t] = v0.y;
                    out[(vb + d) * TT + t + 8] = v1.x;
                    out[(vb + d + 1) * TT + t + 8] = v1.y;
                } else {
                    size_t base = (((size_t)b * HH + head) * TT + t) * HD + d;
                    *(float2*)&out[base] = v0;
                    *(float2*)&out[base + 8 * HD] = v1;
                }
            } else {
                *(float2*)&out[(size_t)row0 * DD + col] = v0;
                *(float2*)&out[(size_t)(row0 + 8) * DD + col] = v1;
            }
        }
    }
}

// ---------------------------------------------------------------------------
// Tensor-core causal flash attention (unchanged except rounded output).
// Grid (T/64, B*H), 128 threads = 4 warps, each warp owns 16 query rows.
// ---------------------------------------------------------------------------
__global__ __launch_bounds__(128) void attn_tc()
{
    __shared__ float sm[3 * 64 * 64];
    float* sQP = sm;
    float* sK  = sm + 4096;
    float* sVt = sm + 8192;

    int bh = blockIdx.y;
    int m0 = blockIdx.x * 64;
    int tid = threadIdx.x;
    int wid = tid >> 5;
    int lane = tid & 31;
    int r = lane >> 2;
    int c = lane & 3;

    const float* Qb  = g_q + (size_t)bh * TT * HD;
    const float* Kb  = g_k + (size_t)bh * TT * HD;
    const float* Vtb = g_v + (size_t)bh * HD * TT;   // [d][T]
    float* Ob        = g_o + (size_t)bh * TT * HD;

#pragma unroll
    for (int i = 0; i < 8; i++) {
        int idx = tid + i * 128;
        int row = idx >> 4;
        int c4 = idx & 15;
        float4 v = *(const float4*)&Qb[(size_t)(m0 + row) * HD + c4 * 4];
        v.x = rtf32(v.x); v.y = rtf32(v.y); v.z = rtf32(v.z); v.w = rtf32(v.w);
        *(float4*)&sQP[SW(row, c4 * 4)] = v;
    }
    __syncthreads();

    int lrow = wid * 16 + r;
    float qf[8][4];
#pragma unroll
    for (int kc = 0; kc < 8; kc++) {
        qf[kc][0] = sQP[SW(lrow,     kc * 8 + c)];
        qf[kc][1] = sQP[SW(lrow + 8, kc * 8 + c)];
        qf[kc][2] = sQP[SW(lrow,     kc * 8 + c + 4)];
        qf[kc][3] = sQP[SW(lrow + 8, kc * 8 + c + 4)];
    }

    float o[8][4];
#pragma unroll
    for (int nt = 0; nt < 8; nt++)
#pragma unroll
        for (int i = 0; i < 4; i++) o[nt][i] = 0.f;

    float mr0 = -INFINITY, mr1 = -INFINITY;
    float l0 = 0.f, l1 = 0.f;
    int rg0 = m0 + lrow;
    int rg1 = rg0 + 8;

    for (int kt = 0; kt <= m0; kt += 64) {
#pragma unroll
        for (int i = 0; i < 8; i++) {
            int idx = tid + i * 128;
            int row = idx >> 4;
            int c4 = idx & 15;
            float4 kv = *(const float4*)&Kb[(size_t)(kt + row) * HD + c4 * 4];
            kv.x = rtf32(kv.x); kv.y = rtf32(kv.y);
            kv.z = rtf32(kv.z); kv.w = rtf32(kv.w);
            *(float4*)&sK[SW(row, c4 * 4)] = kv;
            float4 vv = *(const float4*)&Vtb[(size_t)row * TT + kt + c4 * 4];
            vv.x = rtf32(vv.x); vv.y = rtf32(vv.y);
            vv.z = rtf32(vv.z); vv.w = rtf32(vv.w);
            *(float4*)&sVt[SW(row, c4 * 4)] = vv;
        }
        __syncthreads();

        float s[8][4];
#pragma unroll
        for (int nt = 0; nt < 8; nt++)
#pragma unroll
            for (int i = 0; i < 4; i++) s[nt][i] = 0.f;
#pragma unroll
        for (int kc = 0; kc < 8; kc++) {
            uint32_t af[4];
            af[0] = __float_as_uint(qf[kc][0]);
            af[1] = __float_as_uint(qf[kc][1]);
            af[2] = __float_as_uint(qf[kc][2]);
            af[3] = __float_as_uint(qf[kc][3]);
#pragma unroll
            for (int nt = 0; nt < 8; nt++) {
                uint32_t bf[2];
                bf[0] = __float_as_uint(sK[SW(nt * 8 + r, kc * 8 + c)]);
                bf[1] = __float_as_uint(sK[SW(nt * 8 + r, kc * 8 + c + 4)]);
                mma_tf32(s[nt], af, bf);
            }
        }

        float mx0 = mr0, mx1 = mr1;
        bool diag = (kt == m0);
#pragma unroll
        for (int nt = 0; nt < 8; nt++) {
            s[nt][0] *= SCALE_F; s[nt][1] *= SCALE_F;
            s[nt][2] *= SCALE_F; s[nt][3] *= SCALE_F;
            if (diag) {
                int col0 = kt + nt * 8 + 2 * c;
                if (col0     > rg0) s[nt][0] = -INFINITY;
                if (col0 + 1 > rg0) s[nt][1] = -INFINITY;
                if (col0     > rg1) s[nt][2] = -INFINITY;
                if (col0 + 1 > rg1) s[nt][3] = -INFINITY;
            }
            mx0 = fmaxf(mx0, fmaxf(s[nt][0], s[nt][1]));
            mx1 = fmaxf(mx1, fmaxf(s[nt][2], s[nt][3]));
        }
        mx0 = fmaxf(mx0, __shfl_xor_sync(0xffffffffu, mx0, 1));
        mx0 = fmaxf(mx0, __shfl_xor_sync(0xffffffffu, mx0, 2));
        mx1 = fmaxf(mx1, __shfl_xor_sync(0xffffffffu, mx1, 1));
        mx1 = fmaxf(mx1, __shfl_xor_sync(0xffffffffu, mx1, 2));

        float a0s = __expf(mr0 - mx0);
        float a1s = __expf(mr1 - mx1);
        float sum0 = 0.f, sum1 = 0.f;
#pragma unroll
        for (int nt = 0; nt < 8; nt++) {
            float p0 = rtf32(__expf(s[nt][0] - mx0));
            float p1 = rtf32(__expf(s[nt][1] - mx0));
            float p2 = rtf32(__expf(s[nt][2] - mx1));
            float p3 = rtf32(__expf(s[nt][3] - mx1));
            s[nt][0] = p0; s[nt][1] = p1; s[nt][2] = p2; s[nt][3] = p3;
            sum0 += p0 + p1;
            sum1 += p2 + p3;
        }
        sum0 += __shfl_xor_sync(0xffffffffu, sum0, 1);
        sum0 += __shfl_xor_sync(0xffffffffu, sum0, 2);
        sum1 += __shfl_xor_sync(0xffffffffu, sum1, 1);
        sum1 += __shfl_xor_sync(0xffffffffu, sum1, 2);
        l0 = l0 * a0s + sum0;
        l1 = l1 * a1s + sum1;
#pragma unroll
        for (int nt = 0; nt < 8; nt++) {
            o[nt][0] *= a0s; o[nt][1] *= a0s;
            o[nt][2] *= a1s; o[nt][3] *= a1s;
        }
        mr0 = mx0; mr1 = mx1;

        __syncwarp();
#pragma unroll
        for (int nt = 0; nt < 8; nt++) {
            *(float2*)&sQP[SW(lrow,     nt * 8 + 2 * c)] = make_float2(s[nt][0], s[nt][1]);
            *(float2*)&sQP[SW(lrow + 8, nt * 8 + 2 * c)] = make_float2(s[nt][2], s[nt][3]);
        }
        __syncwarp();
#pragma unroll
        for (int kc = 0; kc < 8; kc++) {
            uint32_t af[4];
            af[0] = __float_as_uint(sQP[SW(lrow,     kc * 8 + c)]);
            af[1] = __float_as_uint(sQP[SW(lrow + 8, kc * 8 + c)]);
            af[2] = __float_as_uint(sQP[SW(lrow,     kc * 8 + c + 4)]);
            af[3] = __float_as_uint(sQP[SW(lrow + 8, kc * 8 + c + 4)]);
#pragma unroll
            for (int nt = 0; nt < 8; nt++) {
                uint32_t bf[2];
                bf[0] = __float_as_uint(sVt[SW(nt * 8 + r, kc * 8 + c)]);
                bf[1] = __float_as_uint(sVt[SW(nt * 8 + r, kc * 8 + c + 4)]);
                mma_tf32(o[nt], af, bf);
            }
        }
        __syncthreads();
    }

    // output pre-rounded to tf32 (feeds MODE 1 GEMM raw)
    float i0 = 1.f / l0, i1 = 1.f / l1;
#pragma unroll
    for (int nt = 0; nt < 8; nt++) {
        *(float2*)&Ob[(size_t)rg0 * HD + nt * 8 + 2 * c] =
            make_float2(rtf32(o[nt][0] * i0), rtf32(o[nt][1] * i0));
        *(float2*)&Ob[(size_t)rg1 * HD + nt * 8 + 2 * c] =
            make_float2(rtf32(o[nt][2] * i1), rtf32(o[nt][3] * i1));
    }
}

extern "C" void kernel_launch(void* const* d_in, const int* in_sizes, int n_in,
                              void* d_out, int out_size)
{
    const float* x  = (const float*)d_in[0];
    const float* Wq = (const float*)d_in[1];
    const float* bq = (const float*)d_in[2];
    const float* Wk = (const float*)d_in[3];
    const float* bk = (const float*)d_in[4];
    const float* Wv = (const float*)d_in[5];
    const float* bv = (const float*)d_in[6];
    const float* Wo = (const float*)d_in[7];
    const float* bo = (const float*)d_in[8];
    float* out = (float*)d_out;

    round_x<<<(BB * TT * DD) / (256 * 4), 256>>>(x);

    dim3 gt(32, 32, 4);
    transpose_w<<<gt, dim3(32, 8)>>>(Wq, Wk, Wv, Wo);

    dim3 g1(DD / 128, (BB * TT) / 128, 3);
    gemm_tc<0><<<g1, 256>>>(bq, bk, bv, nullptr);

    dim3 g2(TT / 64, BB * HH);
    attn_tc<<<g2, 128>>>();

    dim3 g3(DD / 128, (BB * TT) / 128);
    gemm_tc<1><<<g3, 256>>>(bo, nullptr, nullptr, out);
}

// round 7
// speedup vs baseline: 1.1655x; 1.1655x over previous
#include <cuda_runtime.h>
#include <math.h>
#include <stdint.h>

#define BB 4
#define TT 2048
#define DD 1024
#define HH 16
#define HD 64
#define SCALE_F 0.125f   // 1/sqrt(64)

// Scratch. g_q, g_k, g_o: [B, H, T, hd] (tf32-rounded values).
// g_v: [B, H, hd, T] (TRANSPOSED, tf32-rounded).
__device__ float g_q[(size_t)BB * HH * TT * HD];
__device__ float g_k[(size_t)BB * HH * TT * HD];
__device__ float g_v[(size_t)BB * HH * TT * HD];
__device__ float g_o[(size_t)BB * HH * TT * HD];
// W^T scratch: 4 matrices [N=1024][K=1024], tf32-rounded
__device__ float g_wt[(size_t)4 * DD * DD];

__device__ __forceinline__ uint32_t f2tf32(float f) {
    uint32_t r;
    asm("cvt.rna.tf32.f32 %0, %1;" : "=r"(r) : "f"(f));
    return r;
}
__device__ __forceinline__ float rtf32(float f) {
    return __uint_as_float(f2tf32(f));
}

__device__ __forceinline__ void mma_tf32(float* d, const uint32_t* a,
                                         const uint32_t* b) {
    asm volatile(
        "mma.sync.aligned.m16n8k8.row.col.f32.tf32.tf32.f32 "
        "{%0,%1,%2,%3}, {%4,%5,%6,%7}, {%8,%9}, {%0,%1,%2,%3};"
        : "+f"(d[0]), "+f"(d[1]), "+f"(d[2]), "+f"(d[3])
        : "r"(a[0]), "r"(a[1]), "r"(a[2]), "r"(a[3]),
          "r"(b[0]), "r"(b[1]));
}

__device__ __forceinline__ void cpasync16(void* sptr, const void* gptr) {
    uint32_t sa = (uint32_t)__cvta_generic_to_shared(sptr);
    asm volatile("cp.async.ca.shared.global [%0], [%1], 16;"
                 :: "r"(sa), "l"(gptr));
}
#define CP_COMMIT() asm volatile("cp.async.commit_group;" ::: "memory")
#define CP_WAIT0()  asm volatile("cp.async.wait_group 0;" ::: "memory")

// XOR swizzle for 64-col fp32 tiles (attention); 16B-granular
#define SW(row, col) (((row) << 6) + ((col) ^ (((row) & 7) << 2)))

// ---------------------------------------------------------------------------
// Weight transpose: W [K,N] -> g_wt slice [N,K], tf32-rounded
// ---------------------------------------------------------------------------
__global__ __launch_bounds__(256) void transpose_w(
    const float* __restrict__ Wq, const float* __restrict__ Wk,
    const float* __restrict__ Wv, const float* __restrict__ Wo)
{
    const float* src = (blockIdx.z == 0) ? Wq : (blockIdx.z == 1) ? Wk
                     : (blockIdx.z == 2) ? Wv : Wo;
    float* dst = g_wt + (size_t)blockIdx.z * DD * DD;

    __shared__ float tile[32][33];
    int x = blockIdx.x * 32 + threadIdx.x;
    int y0 = blockIdx.y * 32;
#pragma unroll
    for (int j = threadIdx.y; j < 32; j += 8)
        tile[j][threadIdx.x] = src[(size_t)(y0 + j) * DD + x];
    __syncthreads();
    int x2 = y0 + threadIdx.x;
    int y2 = blockIdx.x * 32;
#pragma unroll
    for (int j = threadIdx.y; j < 32; j += 8)
        dst[(size_t)(y2 + j) * DD + x2] = rtf32(tile[threadIdx.x][j]);
}

// ---------------------------------------------------------------------------
// Round-5 style tf32 GEMM (BK=32, single-buffered): C[128x128] = A@Wt^T + b
// MODE 0: A = x arg; z=0 -> g_q, z=1 -> g_k, z=2 -> g_v TRANSPOSED.
//         Epilogue stores tf32-ROUNDED values.
// MODE 1: A gathered from g_o (device symbol), out = d_out [B*T, D] (fp32)
// ---------------------------------------------------------------------------
#define BK 32
#define ASTRIDE 36

template <int MODE>
__global__ __launch_bounds__(256) void gemm_tc(
    const float* __restrict__ Asrc,
    const float* __restrict__ b0, const float* __restrict__ b1,
    const float* __restrict__ b2, float* __restrict__ OutDirect)
{
    __shared__ float sA[128 * ASTRIDE];
    __shared__ float sB[128 * ASTRIDE];

    int tid = threadIdx.x;
    int wid = tid >> 5;
    int lane = tid & 31;
    int warp_m = wid & 1;
    int warp_n = wid >> 1;
    int r = lane >> 2;
    int c = lane & 3;
    int n0 = blockIdx.x * 128;
    int m0 = blockIdx.y * 128;

    const float* Wt;
    const float* bias;
    float* out;
    const float* Ain;
    int zsel = 0;
    if (MODE == 0) {
        zsel = blockIdx.z;
        Wt = g_wt + (size_t)zsel * DD * DD;
        bias = (zsel == 0) ? b0 : (zsel == 1) ? b1 : b2;
        out = (zsel == 0) ? g_q : (zsel == 1) ? g_k : g_v;
        Ain = Asrc;
    } else {
        Wt = g_wt + (size_t)3 * DD * DD;
        bias = b0;
        out = OutDirect;
        Ain = g_o;
    }

    float acc[4][4][4];
#pragma unroll
    for (int mt = 0; mt < 4; mt++)
#pragma unroll
        for (int nt = 0; nt < 4; nt++)
#pragma unroll
            for (int i = 0; i < 4; i++) acc[mt][nt][i] = 0.f;

    for (int kt = 0; kt < DD; kt += BK) {
#pragma unroll
        for (int i = 0; i < 4; i++) {
            int idx = tid + i * 256;
            int row = idx >> 3;
            int c4 = idx & 7;
            const float* srcp;
            if (MODE == 0) {
                srcp = Ain + (size_t)(m0 + row) * DD + kt + c4 * 4;
            } else {
                int m = m0 + row;
                int b = m >> 11;
                int t = m & 2047;
                int h = kt >> 6;
                int d0 = (kt & 63) + c4 * 4;
                srcp = Ain + (((size_t)b * HH + h) * TT + t) * HD + d0;
            }
            float4 v = *(const float4*)srcp;
            uint4 u;
            u.x = f2tf32(v.x); u.y = f2tf32(v.y);
            u.z = f2tf32(v.z); u.w = f2tf32(v.w);
            *(uint4*)&sA[row * ASTRIDE + c4 * 4] = u;

            float4 w = *(const float4*)(Wt + (size_t)(n0 + row) * DD + kt + c4 * 4);
            *(float4*)&sB[row * ASTRIDE + c4 * 4] = w;
        }
        __syncthreads();

#pragma unroll
        for (int ks = 0; ks < 4; ks++) {
            int k0 = ks * 8;
            uint32_t af[4][4], bf[4][2];
#pragma unroll
            for (int mt = 0; mt < 4; mt++) {
                const float* base = &sA[(warp_m * 64 + mt * 16 + r) * ASTRIDE + k0 + c];
                af[mt][0] = __float_as_uint(base[0]);
                af[mt][1] = __float_as_uint(base[8 * ASTRIDE]);
                af[mt][2] = __float_as_uint(base[4]);
                af[mt][3] = __float_as_uint(base[8 * ASTRIDE + 4]);
            }
#pragma unroll
            for (int nt = 0; nt < 4; nt++) {
                const float* base = &sB[(warp_n * 32 + nt * 8 + r) * ASTRIDE + k0 + c];
                bf[nt][0] = __float_as_uint(base[0]);
                bf[nt][1] = __float_as_uint(base[4]);
            }
#pragma unroll
            for (int mt = 0; mt < 4; mt++)
#pragma unroll
                for (int nt = 0; nt < 4; nt++)
                    mma_tf32(acc[mt][nt], af[mt], bf[nt]);
        }
        __syncthreads();
    }

#pragma unroll
    for (int nt = 0; nt < 4; nt++) {
        int col = n0 + warp_n * 32 + nt * 8 + c * 2;
        float bx = __ldg(&bias[col]);
        float by = __ldg(&bias[col + 1]);
#pragma unroll
        for (int mt = 0; mt < 4; mt++) {
            int row0 = m0 + warp_m * 64 + mt * 16 + r;
            float2 v0, v1;
            if (MODE == 0) {
                v0.x = rtf32(acc[mt][nt][0] + bx);
                v0.y = rtf32(acc[mt][nt][1] + by);
                v1.x = rtf32(acc[mt][nt][2] + bx);
                v1.y = rtf32(acc[mt][nt][3] + by);
                int head = col >> 6;
                int d = col & 63;
                int b = row0 >> 11;
                int t = row0 & 2047;
                if (zsel == 2) {
                    size_t vb = ((size_t)b * HH + head) * HD;
                    out[(vb + d) * TT + t] = v0.x;
                    out[(vb + d + 1) * TT + t] = v0.y;
                    out[(vb + d) * TT + t + 8] = v1.x;
                    out[(vb + d + 1) * TT + t + 8] = v1.y;
                } else {
                    size_t base = (((size_t)b * HH + head) * TT + t) * HD + d;
                    *(float2*)&out[base] = v0;
                    *(float2*)&out[base + 8 * HD] = v1;
                }
            } else {
                v0.x = acc[mt][nt][0] + bx;
                v0.y = acc[mt][nt][1] + by;
                v1.x = acc[mt][nt][2] + bx;
                v1.y = acc[mt][nt][3] + by;
                *(float2*)&out[(size_t)row0 * DD + col] = v0;
                *(float2*)&out[(size_t)(row0 + 8) * DD + col] = v1;
            }
        }
    }
}

// ---------------------------------------------------------------------------
// Tensor-core causal flash attention, Q-tile 128, 4 warps (2 m-frags/warp).
// K/V tiles (64 keys) double-buffered via cp.async; 1 barrier per tile.
// Dynamic smem 96KB: sP 32K | sK[2] 32K | sV[2] 32K.
// Q/K/V in gmem are pre-rounded to tf32 -> raw copies, no cvt in loop.
// ---------------------------------------------------------------------------
__global__ __launch_bounds__(128) void attn_tc()
{
    extern __shared__ float sm[];
    float* sP = sm;                      // 128x64
    // sK[st] = sm + 8192 + st*4096 ; sV[st] = sm + 16384 + st*4096

    int bh = blockIdx.y;
    int m0 = blockIdx.x * 128;
    int tid = threadIdx.x;
    int wid = tid >> 5;
    int lane = tid & 31;
    int r = lane >> 2;
    int c = lane & 3;

    const float* Qb  = g_q + (size_t)bh * TT * HD;
    const float* Kb  = g_k + (size_t)bh * TT * HD;
    const float* Vtb = g_v + (size_t)bh * HD * TT;   // [d][T]
    float* Ob        = g_o + (size_t)bh * TT * HD;

    const int NT = blockIdx.x * 2 + 2;   // number of 64-key tiles

    // ---- issue K/V tile 0 loads ----
#pragma unroll
    for (int i = 0; i < 8; i++) {
        int idx = tid + i * 128;
        int row = idx >> 4;
        int c4 = idx & 15;
        cpasync16(&sm[8192 + SW(row, c4 * 4)],
                  &Kb[(size_t)row * HD + c4 * 4]);
        cpasync16(&sm[16384 + SW(row, c4 * 4)],
                  &Vtb[(size_t)row * TT + c4 * 4]);
    }
    CP_COMMIT();

    // ---- Q tile -> sP (raw; already rounded) ----
#pragma unroll
    for (int i = 0; i < 16; i++) {
        int idx = tid + i * 128;
        int row = idx >> 4;
        int c4 = idx & 15;
        *(float4*)&sP[SW(row, c4 * 4)] =
            *(const float4*)&Qb[(size_t)(m0 + row) * HD + c4 * 4];
    }
    __syncthreads();

    // per-warp Q fragments: two m-frags at rows wid*32+mt*16 + {r, r+8}
    uint32_t qf[2][8][4];
#pragma unroll
    for (int mt = 0; mt < 2; mt++) {
        int lr = wid * 32 + mt * 16 + r;
#pragma unroll
        for (int kc = 0; kc < 8; kc++) {
            qf[mt][kc][0] = __float_as_uint(sP[SW(lr,     kc * 8 + c)]);
            qf[mt][kc][1] = __float_as_uint(sP[SW(lr + 8, kc * 8 + c)]);
            qf[mt][kc][2] = __float_as_uint(sP[SW(lr,     kc * 8 + c + 4)]);
            qf[mt][kc][3] = __float_as_uint(sP[SW(lr + 8, kc * 8 + c + 4)]);
        }
    }
    __syncthreads();   // everyone has Q frags before sP is reused for P

    float o[2][8][4];
#pragma unroll
    for (int mt = 0; mt < 2; mt++)
#pragma unroll
        for (int nt = 0; nt < 8; nt++)
#pragma unroll
            for (int i = 0; i < 4; i++) o[mt][nt][i] = 0.f;

    float mrun[2][2] = {{-INFINITY, -INFINITY}, {-INFINITY, -INFINITY}};
    float lrun[2][2] = {{0.f, 0.f}, {0.f, 0.f}};
    int rg[2][2];
#pragma unroll
    for (int mt = 0; mt < 2; mt++) {
        rg[mt][0] = m0 + wid * 32 + mt * 16 + r;
        rg[mt][1] = rg[mt][0] + 8;
    }

    for (int s = 0; s < NT; s++) {
        int kt = s * 64;
        CP_WAIT0();
        __syncthreads();          // tile s visible; all warps done with s-1

        // prefetch tile s+1 into the other buffer (freed by barrier above)
        if (s + 1 < NT) {
            int kt2 = (s + 1) * 64;
            int st2 = (s + 1) & 1;
#pragma unroll
            for (int i = 0; i < 8; i++) {
                int idx = tid + i * 128;
                int row = idx >> 4;
                int c4 = idx & 15;
                cpasync16(&sm[8192 + st2 * 4096 + SW(row, c4 * 4)],
                          &Kb[(size_t)(kt2 + row) * HD + c4 * 4]);
                cpasync16(&sm[16384 + st2 * 4096 + SW(row, c4 * 4)],
                          &Vtb[(size_t)row * TT + kt2 + c4 * 4]);
            }
            CP_COMMIT();
        }

        const float* sK = sm + 8192 + (s & 1) * 4096;
        const float* sV = sm + 16384 + (s & 1) * 4096;

        // ---- S = Q K^T (both m-frags share each K fragment) ----
        float sc[2][8][4];
#pragma unroll
        for (int mt = 0; mt < 2; mt++)
#pragma unroll
            for (int nt = 0; nt < 8; nt++)
#pragma unroll
                for (int i = 0; i < 4; i++) sc[mt][nt][i] = 0.f;
#pragma unroll
        for (int kc = 0; kc < 8; kc++) {
#pragma unroll
            for (int nt = 0; nt < 8; nt++) {
                uint32_t bf[2];
                bf[0] = __float_as_uint(sK[SW(nt * 8 + r, kc * 8 + c)]);
                bf[1] = __float_as_uint(sK[SW(nt * 8 + r, kc * 8 + c + 4)]);
                mma_tf32(sc[0][nt], qf[0][kc], bf);
                mma_tf32(sc[1][nt], qf[1][kc], bf);
            }
        }

        // ---- scale, mask, online softmax, P write, rescale o ----
        bool need_mask = (kt + 63 > m0);
        __syncwarp();
#pragma unroll
        for (int mt = 0; mt < 2; mt++) {
            float mx0 = mrun[mt][0], mx1 = mrun[mt][1];
#pragma unroll
            for (int nt = 0; nt < 8; nt++) {
                float* sv = sc[mt][nt];
                sv[0] *= SCALE_F; sv[1] *= SCALE_F;
                sv[2] *= SCALE_F; sv[3] *= SCALE_F;
                if (need_mask) {
                    int col0 = kt + nt * 8 + 2 * c;
                    if (col0     > rg[mt][0]) sv[0] = -INFINITY;
                    if (col0 + 1 > rg[mt][0]) sv[1] = -INFINITY;
                    if (col0     > rg[mt][1]) sv[2] = -INFINITY;
                    if (col0 + 1 > rg[mt][1]) sv[3] = -INFINITY;
                }
                mx0 = fmaxf(mx0, fmaxf(sv[0], sv[1]));
                mx1 = fmaxf(mx1, fmaxf(sv[2], sv[3]));
            }
            mx0 = fmaxf(mx0, __shfl_xor_sync(0xffffffffu, mx0, 1));
            mx0 = fmaxf(mx0, __shfl_xor_sync(0xffffffffu, mx0, 2));
            mx1 = fmaxf(mx1, __shfl_xor_sync(0xffffffffu, mx1, 1));
            mx1 = fmaxf(mx1, __shfl_xor_sync(0xffffffffu, mx1, 2));

            float a0 = __expf(mrun[mt][0] - mx0);
            float a1 = __expf(mrun[mt][1] - mx1);
            float sum0 = 0.f, sum1 = 0.f;
            int lr = wid * 32 + mt * 16 + r;
#pragma unroll
            for (int nt = 0; nt < 8; nt++) {
                float p0 = rtf32(__expf(sc[mt][nt][0] - mx0));
                float p1 = rtf32(__expf(sc[mt][nt][1] - mx0));
                float p2 = rtf32(__expf(sc[mt][nt][2] - mx1));
                float p3 = rtf32(__expf(sc[mt][nt][3] - mx1));
                sum0 += p0 + p1;
                sum1 += p2 + p3;
                *(float2*)&sP[SW(lr,     nt * 8 + 2 * c)] = make_float2(p0, p1);
                *(float2*)&sP[SW(lr + 8, nt * 8 + 2 * c)] = make_float2(p2, p3);
            }
            sum0 += __shfl_xor_sync(0xffffffffu, sum0, 1);
            sum0 += __shfl_xor_sync(0xffffffffu, sum0, 2);
            sum1 += __shfl_xor_sync(0xffffffffu, sum1, 1);
            sum1 += __shfl_xor_sync(0xffffffffu, sum1, 2);
            lrun[mt][0] = lrun[mt][0] * a0 + sum0;
            lrun[mt][1] = lrun[mt][1] * a1 + sum1;
#pragma unroll
            for (int nt = 0; nt < 8; nt++) {
                o[mt][nt][0] *= a0; o[mt][nt][1] *= a0;
                o[mt][nt][2] *= a1; o[mt][nt][3] *= a1;
            }
            mrun[mt][0] = mx0;
            mrun[mt][1] = mx1;
        }
        __syncwarp();

        // ---- O += P V (V fragments shared across both m-frags) ----
#pragma unroll
        for (int kc = 0; kc < 8; kc++) {
            uint32_t af[2][4];
#pragma unroll
            for (int mt = 0; mt < 2; mt++) {
                int lr = wid * 32 + mt * 16 + r;
                af[mt][0] = __float_as_uint(sP[SW(lr,     kc * 8 + c)]);
                af[mt][1] = __float_as_uint(sP[SW(lr + 8, kc * 8 + c)]);
                af[mt][2] = __float_as_uint(sP[SW(lr,     kc * 8 + c + 4)]);
                af[mt][3] = __float_as_uint(sP[SW(lr + 8, kc * 8 + c + 4)]);
            }
#pragma unroll
            for (int nt = 0; nt < 8; nt++) {
                uint32_t bf[2];
                bf[0] = __float_as_uint(sV[SW(nt * 8 + r, kc * 8 + c)]);
                bf[1] = __float_as_uint(sV[SW(nt * 8 + r, kc * 8 + c + 4)]);
                mma_tf32(o[0][nt], af[0], bf);
                mma_tf32(o[1][nt], af[1], bf);
            }
        }
    }

    // ---- output (tf32-rounded; feeds MODE 1 GEMM) ----
#pragma unroll
    for (int mt = 0; mt < 2; mt++) {
        float i0 = 1.f / lrun[mt][0];
        float i1 = 1.f / lrun[mt][1];
#pragma unroll
        for (int nt = 0; nt < 8; nt++) {
            *(float2*)&Ob[(size_t)rg[mt][0] * HD + nt * 8 + 2 * c] =
                make_float2(rtf32(o[mt][nt][0] * i0), rtf32(o[mt][nt][1] * i0));
            *(float2*)&Ob[(size_t)rg[mt][1] * HD + nt * 8 + 2 * c] =
                make_float2(rtf32(o[mt][nt][2] * i1), rtf32(o[mt][nt][3] * i1));
        }
    }
}

extern "C" void kernel_launch(void* const* d_in, const int* in_sizes, int n_in,
                              void* d_out, int out_size)
{
    const float* x  = (const float*)d_in[0];
    const float* Wq = (const float*)d_in[1];
    const float* bq = (const float*)d_in[2];
    const float* Wk = (const float*)d_in[3];
    const float* bk = (const float*)d_in[4];
    const float* Wv = (const float*)d_in[5];
    const float* bv = (const float*)d_in[6];
    const float* Wo = (const float*)d_in[7];
    const float* bo = (const float*)d_in[8];
    float* out = (float*)d_out;

    cudaFuncSetAttribute(attn_tc, cudaFuncAttributeMaxDynamicSharedMemorySize,
                         96 * 1024);

    dim3 gt(32, 32, 4);
    transpose_w<<<gt, dim3(32, 8)>>>(Wq, Wk, Wv, Wo);

    dim3 g1(DD / 128, (BB * TT) / 128, 3);
    gemm_tc<0><<<g1, 256>>>(x, bq, bk, bv, nullptr);

    dim3 g2(TT / 128, BB * HH);              // 16 x 64
    attn_tc<<<g2, 128, 96 * 1024>>>();

    dim3 g3(DD / 128, (BB * TT) / 128);
    gemm_tc<1><<<g3, 256>>>(nullptr, bo, nullptr, nullptr, out);
}

// round 8
// speedup vs baseline: 1.2145x; 1.0421x over previous
#include <cuda_runtime.h>
#include <math.h>
#include <stdint.h>

#define BB 4
#define TT 2048
#define DD 1024
#define HH 16
#define HD 64
#define SCALE_F 0.125f   // 1/sqrt(64)

// Scratch. g_q, g_k, g_o: [B, H, T, hd] (tf32-rounded values).
// g_v: [B, H, hd, T] (TRANSPOSED, tf32-rounded).
__device__ float g_q[(size_t)BB * HH * TT * HD];
__device__ float g_k[(size_t)BB * HH * TT * HD];
__device__ float g_v[(size_t)BB * HH * TT * HD];
__device__ float g_o[(size_t)BB * HH * TT * HD];
// Pre-rounded X: [B*T, D]
__device__ float g_x[(size_t)BB * TT * DD];
// W^T scratch: 4 matrices [N=1024][K=1024], tf32-rounded
__device__ float g_wt[(size_t)4 * DD * DD];

__device__ __forceinline__ uint32_t f2tf32(float f) {
    uint32_t r;
    asm("cvt.rna.tf32.f32 %0, %1;" : "=r"(r) : "f"(f));
    return r;
}
__device__ __forceinline__ float rtf32(float f) {
    return __uint_as_float(f2tf32(f));
}

__device__ __forceinline__ void mma_tf32(float* d, const uint32_t* a,
                                         const uint32_t* b) {
    asm volatile(
        "mma.sync.aligned.m16n8k8.row.col.f32.tf32.tf32.f32 "
        "{%0,%1,%2,%3}, {%4,%5,%6,%7}, {%8,%9}, {%0,%1,%2,%3};"
        : "+f"(d[0]), "+f"(d[1]), "+f"(d[2]), "+f"(d[3])
        : "r"(a[0]), "r"(a[1]), "r"(a[2]), "r"(a[3]),
          "r"(b[0]), "r"(b[1]));
}

__device__ __forceinline__ void cpasync16(void* sptr, const void* gptr) {
    uint32_t sa = (uint32_t)__cvta_generic_to_shared(sptr);
    asm volatile("cp.async.ca.shared.global [%0], [%1], 16;"
                 :: "r"(sa), "l"(gptr));
}
#define CP_COMMIT() asm volatile("cp.async.commit_group;" ::: "memory")
#define CP_WAIT0()  asm volatile("cp.async.wait_group 0;" ::: "memory")

// XOR swizzle for 64-col fp32 tiles (attention); 16B-granular
#define SW(row, col) (((row) << 6) + ((col) ^ (((row) & 7) << 2)))

// ---------------------------------------------------------------------------
// Pre-round X to tf32
// ---------------------------------------------------------------------------
__global__ __launch_bounds__(256) void round_x(const float* __restrict__ x)
{
    size_t i = ((size_t)blockIdx.x * 256 + threadIdx.x) * 4;
    float4 v = *(const float4*)&x[i];
    uint4 u;
    u.x = f2tf32(v.x); u.y = f2tf32(v.y);
    u.z = f2tf32(v.z); u.w = f2tf32(v.w);
    *(uint4*)&g_x[i] = u;
}

// ---------------------------------------------------------------------------
// Weight transpose: W [K,N] -> g_wt slice [N,K], tf32-rounded
// ---------------------------------------------------------------------------
__global__ __launch_bounds__(256) void transpose_w(
    const float* __restrict__ Wq, const float* __restrict__ Wk,
    const float* __restrict__ Wv, const float* __restrict__ Wo)
{
    const float* src = (blockIdx.z == 0) ? Wq : (blockIdx.z == 1) ? Wk
                     : (blockIdx.z == 2) ? Wv : Wo;
    float* dst = g_wt + (size_t)blockIdx.z * DD * DD;

    __shared__ float tile[32][33];
    int x = blockIdx.x * 32 + threadIdx.x;
    int y0 = blockIdx.y * 32;
#pragma unroll
    for (int j = threadIdx.y; j < 32; j += 8)
        tile[j][threadIdx.x] = src[(size_t)(y0 + j) * DD + x];
    __syncthreads();
    int x2 = y0 + threadIdx.x;
    int y2 = blockIdx.x * 32;
#pragma unroll
    for (int j = threadIdx.y; j < 32; j += 8)
        dst[(size_t)(y2 + j) * DD + x2] = rtf32(tile[threadIdx.x][j]);
}

// ---------------------------------------------------------------------------
// cp.async 2-stage tf32 GEMM, BK=32: C[128x128] = A @ Wt^T + b
// One __syncthreads per k-iteration; 64 MMAs between barriers.
// MODE 0: A = g_x (pre-rounded); z=0 -> g_q, z=1 -> g_k, z=2 -> g_v TRANS.
//         Epilogue stores tf32-ROUNDED values.
// MODE 1: A gathered from g_o (pre-rounded), out = d_out [B*T, D] (fp32)
// Dynamic smem: 2 stages x (A 128x36 + B 128x36) floats = 72 KB.
// ---------------------------------------------------------------------------
#define BK 32
#define ASTRIDE 36
#define TILE_F (128 * ASTRIDE)          // 4608 floats

template <int MODE>
__global__ __launch_bounds__(256) void gemm_tc(
    const float* __restrict__ b0, const float* __restrict__ b1,
    const float* __restrict__ b2, float* __restrict__ OutDirect)
{
    extern __shared__ float smd[];
    // layout: A stage0 | A stage1 | B stage0 | B stage1

    int tid = threadIdx.x;
    int wid = tid >> 5;
    int lane = tid & 31;
    int warp_m = wid & 1;
    int warp_n = wid >> 1;
    int r = lane >> 2;
    int c = lane & 3;
    int n0 = blockIdx.x * 128;
    int m0 = blockIdx.y * 128;

    const float* Wt;
    const float* bias;
    float* out;
    const float* Ain;
    int zsel = 0;
    if (MODE == 0) {
        zsel = blockIdx.z;
        Wt = g_wt + (size_t)zsel * DD * DD;
        bias = (zsel == 0) ? b0 : (zsel == 1) ? b1 : b2;
        out = (zsel == 0) ? g_q : (zsel == 1) ? g_k : g_v;
        Ain = g_x;
    } else {
        Wt = g_wt + (size_t)3 * DD * DD;
        bias = b0;
        out = OutDirect;
        Ain = g_o;
    }

    auto load_stage = [&](int st, int kt) {
#pragma unroll
        for (int i = 0; i < 4; i++) {
            int idx = tid + i * 256;        // 0..1023
            int row = idx >> 3;             // 0..127
            int c4 = idx & 7;               // 0..7
            const float* srcA;
            if (MODE == 0) {
                srcA = Ain + (size_t)(m0 + row) * DD + kt + c4 * 4;
            } else {
                int m = m0 + row;
                int b = m >> 11;
                int t = m & 2047;
                int h = kt >> 6;
                int d0 = (kt & 63) + c4 * 4;
                srcA = Ain + (((size_t)b * HH + h) * TT + t) * HD + d0;
            }
            cpasync16(&smd[st * TILE_F + row * ASTRIDE + c4 * 4], srcA);
            cpasync16(&smd[2 * TILE_F + st * TILE_F + row * ASTRIDE + c4 * 4],
                      Wt + (size_t)(n0 + row) * DD + kt + c4 * 4);
        }
        CP_COMMIT();
    };

    float acc[4][4][4];
#pragma unroll
    for (int mt = 0; mt < 4; mt++)
#pragma unroll
        for (int nt = 0; nt < 4; nt++)
#pragma unroll
            for (int i = 0; i < 4; i++) acc[mt][nt][i] = 0.f;

    const int NIT = DD / BK;   // 32
    load_stage(0, 0);

    for (int it = 0; it < NIT; it++) {
        CP_WAIT0();
        __syncthreads();        // stage it published; stage it^1 free

        if (it + 1 < NIT)
            load_stage((it + 1) & 1, (it + 1) * BK);

        const float* cA = &smd[(it & 1) * TILE_F];
        const float* cB = &smd[2 * TILE_F + (it & 1) * TILE_F];
#pragma unroll
        for (int ks = 0; ks < 4; ks++) {
            int k0 = ks * 8;
            uint32_t af[4][4], bf[4][2];
#pragma unroll
            for (int mt = 0; mt < 4; mt++) {
                const float* base = &cA[(warp_m * 64 + mt * 16 + r) * ASTRIDE + k0 + c];
                af[mt][0] = __float_as_uint(base[0]);
                af[mt][1] = __float_as_uint(base[8 * ASTRIDE]);
                af[mt][2] = __float_as_uint(base[4]);
                af[mt][3] = __float_as_uint(base[8 * ASTRIDE + 4]);
            }
#pragma unroll
            for (int nt = 0; nt < 4; nt++) {
                const float* base = &cB[(warp_n * 32 + nt * 8 + r) * ASTRIDE + k0 + c];
                bf[nt][0] = __float_as_uint(base[0]);
                bf[nt][1] = __float_as_uint(base[4]);
            }
#pragma unroll
            for (int mt = 0; mt < 4; mt++)
#pragma unroll
                for (int nt = 0; nt < 4; nt++)
                    mma_tf32(acc[mt][nt], af[mt], bf[nt]);
        }
    }

#pragma unroll
    for (int nt = 0; nt < 4; nt++) {
        int col = n0 + warp_n * 32 + nt * 8 + c * 2;
        float bx = __ldg(&bias[col]);
        float by = __ldg(&bias[col + 1]);
#pragma unroll
        for (int mt = 0; mt < 4; mt++) {
            int row0 = m0 + warp_m * 64 + mt * 16 + r;
            float2 v0, v1;
            if (MODE == 0) {
                v0.x = rtf32(acc[mt][nt][0] + bx);
                v0.y = rtf32(acc[mt][nt][1] + by);
                v1.x = rtf32(acc[mt][nt][2] + bx);
                v1.y = rtf32(acc[mt][nt][3] + by);
                int head = col >> 6;
                int d = col & 63;
                int b = row0 >> 11;
                int t = row0 & 2047;
                if (zsel == 2) {
                    size_t vb = ((size_t)b * HH + head) * HD;
                    out[(vb + d) * TT + t] = v0.x;
                    out[(vb + d + 1) * TT + t] = v0.y;
                    out[(vb + d) * TT + t + 8] = v1.x;
                    out[(vb + d + 1) * TT + t + 8] = v1.y;
                } else {
                    size_t base = (((size_t)b * HH + head) * TT + t) * HD + d;
                    *(float2*)&out[base] = v0;
                    *(float2*)&out[base + 8 * HD] = v1;
                }
            } else {
                v0.x = acc[mt][nt][0] + bx;
                v0.y = acc[mt][nt][1] + by;
                v1.x = acc[mt][nt][2] + bx;
                v1.y = acc[mt][nt][3] + by;
                *(float2*)&out[(size_t)row0 * DD + col] = v0;
                *(float2*)&out[(size_t)(row0 + 8) * DD + col] = v1;
            }
        }
    }
}

// ---------------------------------------------------------------------------
// Tensor-core causal flash attention, Q-tile 128, 4 warps (2 m-frags/warp).
// K/V tiles (64 keys) double-buffered via cp.async; 1 barrier per tile.
// Dynamic smem 96KB: sP 32K | sK[2] 32K | sV[2] 32K.  (unchanged)
// ---------------------------------------------------------------------------
__global__ __launch_bounds__(128) void attn_tc()
{
    extern __shared__ float sm[];
    float* sP = sm;                      // 128x64

    int bh = blockIdx.y;
    int m0 = blockIdx.x * 128;
    int tid = threadIdx.x;
    int wid = tid >> 5;
    int lane = tid & 31;
    int r = lane >> 2;
    int c = lane & 3;

    const float* Qb  = g_q + (size_t)bh * TT * HD;
    const float* Kb  = g_k + (size_t)bh * TT * HD;
    const float* Vtb = g_v + (size_t)bh * HD * TT;   // [d][T]
    float* Ob        = g_o + (size_t)bh * TT * HD;

    const int NT = blockIdx.x * 2 + 2;

#pragma unroll
    for (int i = 0; i < 8; i++) {
        int idx = tid + i * 128;
        int row = idx >> 4;
        int c4 = idx & 15;
        cpasync16(&sm[8192 + SW(row, c4 * 4)],
                  &Kb[(size_t)row * HD + c4 * 4]);
        cpasync16(&sm[16384 + SW(row, c4 * 4)],
                  &Vtb[(size_t)row * TT + c4 * 4]);
    }
    CP_COMMIT();

#pragma unroll
    for (int i = 0; i < 16; i++) {
        int idx = tid + i * 128;
        int row = idx >> 4;
        int c4 = idx & 15;
        *(float4*)&sP[SW(row, c4 * 4)] =
            *(const float4*)&Qb[(size_t)(m0 + row) * HD + c4 * 4];
    }
    __syncthreads();

    uint32_t qf[2][8][4];
#pragma unroll
    for (int mt = 0; mt < 2; mt++) {
        int lr = wid * 32 + mt * 16 + r;
#pragma unroll
        for (int kc = 0; kc < 8; kc++) {
            qf[mt][kc][0] = __float_as_uint(sP[SW(lr,     kc * 8 + c)]);
            qf[mt][kc][1] = __float_as_uint(sP[SW(lr + 8, kc * 8 + c)]);
            qf[mt][kc][2] = __float_as_uint(sP[SW(lr,     kc * 8 + c + 4)]);
            qf[mt][kc][3] = __float_as_uint(sP[SW(lr + 8, kc * 8 + c + 4)]);
        }
    }
    __syncthreads();

    float o[2][8][4];
#pragma unroll
    for (int mt = 0; mt < 2; mt++)
#pragma unroll
        for (int nt = 0; nt < 8; nt++)
#pragma unroll
            for (int i = 0; i < 4; i++) o[mt][nt][i] = 0.f;

    float mrun[2][2] = {{-INFINITY, -INFINITY}, {-INFINITY, -INFINITY}};
    float lrun[2][2] = {{0.f, 0.f}, {0.f, 0.f}};
    int rg[2][2];
#pragma unroll
    for (int mt = 0; mt < 2; mt++) {
        rg[mt][0] = m0 + wid * 32 + mt * 16 + r;
        rg[mt][1] = rg[mt][0] + 8;
    }

    for (int s = 0; s < NT; s++) {
        int kt = s * 64;
        CP_WAIT0();
        __syncthreads();

        if (s + 1 < NT) {
            int kt2 = (s + 1) * 64;
            int st2 = (s + 1) & 1;
#pragma unroll
            for (int i = 0; i < 8; i++) {
                int idx = tid + i * 128;
                int row = idx >> 4;
                int c4 = idx & 15;
                cpasync16(&sm[8192 + st2 * 4096 + SW(row, c4 * 4)],
                          &Kb[(size_t)(kt2 + row) * HD + c4 * 4]);
                cpasync16(&sm[16384 + st2 * 4096 + SW(row, c4 * 4)],
                          &Vtb[(size_t)row * TT + kt2 + c4 * 4]);
            }
            CP_COMMIT();
        }

        const float* sK = sm + 8192 + (s & 1) * 4096;
        const float* sV = sm + 16384 + (s & 1) * 4096;

        float sc[2][8][4];
#pragma unroll
        for (int mt = 0; mt < 2; mt++)
#pragma unroll
            for (int nt = 0; nt < 8; nt++)
#pragma unroll
                for (int i = 0; i < 4; i++) sc[mt][nt][i] = 0.f;
#pragma unroll
        for (int kc = 0; kc < 8; kc++) {
#pragma unroll
            for (int nt = 0; nt < 8; nt++) {
                uint32_t bf[2];
                bf[0] = __float_as_uint(sK[SW(nt * 8 + r, kc * 8 + c)]);
                bf[1] = __float_as_uint(sK[SW(nt * 8 + r, kc * 8 + c + 4)]);
                mma_tf32(sc[0][nt], qf[0][kc], bf);
                mma_tf32(sc[1][nt], qf[1][kc], bf);
            }
        }

        bool need_mask = (kt + 63 > m0);
        __syncwarp();
#pragma unroll
        for (int mt = 0; mt < 2; mt++) {
            float mx0 = mrun[mt][0], mx1 = mrun[mt][1];
#pragma unroll
            for (int nt = 0; nt < 8; nt++) {
                float* sv = sc[mt][nt];
                sv[0] *= SCALE_F; sv[1] *= SCALE_F;
                sv[2] *= SCALE_F; sv[3] *= SCALE_F;
                if (need_mask) {
                    int col0 = kt + nt * 8 + 2 * c;
                    if (col0     > rg[mt][0]) sv[0] = -INFINITY;
                    if (col0 + 1 > rg[mt][0]) sv[1] = -INFINITY;
                    if (col0     > rg[mt][1]) sv[2] = -INFINITY;
                    if (col0 + 1 > rg[mt][1]) sv[3] = -INFINITY;
                }
                mx0 = fmaxf(mx0, fmaxf(sv[0], sv[1]));
                mx1 = fmaxf(mx1, fmaxf(sv[2], sv[3]));
            }
            mx0 = fmaxf(mx0, __shfl_xor_sync(0xffffffffu, mx0, 1));
            mx0 = fmaxf(mx0, __shfl_xor_sync(0xffffffffu, mx0, 2));
            mx1 = fmaxf(mx1, __shfl_xor_sync(0xffffffffu, mx1, 1));
            mx1 = fmaxf(mx1, __shfl_xor_sync(0xffffffffu, mx1, 2));

            float a0 = __expf(mrun[mt][0] - mx0);
            float a1 = __expf(mrun[mt][1] - mx1);
            float sum0 = 0.f, sum1 = 0.f;
            int lr = wid * 32 + mt * 16 + r;
#pragma unroll
            for (int nt = 0; nt < 8; nt++) {
                float p0 = rtf32(__expf(sc[mt][nt][0] - mx0));
                float p1 = rtf32(__expf(sc[mt][nt][1] - mx0));
                float p2 = rtf32(__expf(sc[mt][nt][2] - mx1));
                float p3 = rtf32(__expf(sc[mt][nt][3] - mx1));
                sum0 += p0 + p1;
                sum1 += p2 + p3;
                *(float2*)&sP[SW(lr,     nt * 8 + 2 * c)] = make_float2(p0, p1);
                *(float2*)&sP[SW(lr + 8, nt * 8 + 2 * c)] = make_float2(p2, p3);
            }
            sum0 += __shfl_xor_sync(0xffffffffu, sum0, 1);
            sum0 += __shfl_xor_sync(0xffffffffu, sum0, 2);
            sum1 += __shfl_xor_sync(0xffffffffu, sum1, 1);
            sum1 += __shfl_xor_sync(0xffffffffu, sum1, 2);
            lrun[mt][0] = lrun[mt][0] * a0 + sum0;
            lrun[mt][1] = lrun[mt][1] * a1 + sum1;
#pragma unroll
            for (int nt = 0; nt < 8; nt++) {
                o[mt][nt][0] *= a0; o[mt][nt][1] *= a0;
                o[mt][nt][2] *= a1; o[mt][nt][3] *= a1;
            }
            mrun[mt][0] = mx0;
            mrun[mt][1] = mx1;
        }
        __syncwarp();

#pragma unroll
        for (int kc = 0; kc < 8; kc++) {
            uint32_t af[2][4];
#pragma unroll
            for (int mt = 0; mt < 2; mt++) {
                int lr = wid * 32 + mt * 16 + r;
                af[mt][0] = __float_as_uint(sP[SW(lr,     kc * 8 + c)]);
                af[mt][1] = __float_as_uint(sP[SW(lr + 8, kc * 8 + c)]);
                af[mt][2] = __float_as_uint(sP[SW(lr,     kc * 8 + c + 4)]);
                af[mt][3] = __float_as_uint(sP[SW(lr + 8, kc * 8 + c + 4)]);
            }
#pragma unroll
            for (int nt = 0; nt < 8; nt++) {
                uint32_t bf[2];
                bf[0] = __float_as_uint(sV[SW(nt * 8 + r, kc * 8 + c)]);
                bf[1] = __float_as_uint(sV[SW(nt * 8 + r, kc * 8 + c + 4)]);
                mma_tf32(o[0][nt], af[0], bf);
                mma_tf32(o[1][nt], af[1], bf);
            }
        }
    }

#pragma unroll
    for (int mt = 0; mt < 2; mt++) {
        float i0 = 1.f / lrun[mt][0];
        float i1 = 1.f / lrun[mt][1];
#pragma unroll
        for (int nt = 0; nt < 8; nt++) {
            *(float2*)&Ob[(size_t)rg[mt][0] * HD + nt * 8 + 2 * c] =
                make_float2(rtf32(o[mt][nt][0] * i0), rtf32(o[mt][nt][1] * i0));
            *(float2*)&Ob[(size_t)rg[mt][1] * HD + nt * 8 + 2 * c] =
                make_float2(rtf32(o[mt][nt][2] * i1), rtf32(o[mt][nt][3] * i1));
        }
    }
}

extern "C" void kernel_launch(void* const* d_in, const int* in_sizes, int n_in,
                              void* d_out, int out_size)
{
    const float* x  = (const float*)d_in[0];
    const float* Wq = (const float*)d_in[1];
    const float* bq = (const float*)d_in[2];
    const float* Wk = (const float*)d_in[3];
    const float* bk = (const float*)d_in[4];
    const float* Wv = (const float*)d_in[5];
    const float* bv = (const float*)d_in[6];
    const float* Wo = (const float*)d_in[7];
    const float* bo = (const float*)d_in[8];
    float* out = (float*)d_out;

    const int GEMM_SMEM = 4 * TILE_F * 4;   // 73728 B
    cudaFuncSetAttribute(gemm_tc<0>, cudaFuncAttributeMaxDynamicSharedMemorySize,
                         GEMM_SMEM);
    cudaFuncSetAttribute(gemm_tc<1>, cudaFuncAttributeMaxDynamicSharedMemorySize,
                         GEMM_SMEM);
    cudaFuncSetAttribute(attn_tc, cudaFuncAttributeMaxDynamicSharedMemorySize,
                         96 * 1024);

    round_x<<<(BB * TT * DD) / (256 * 4), 256>>>(x);

    dim3 gt(32, 32, 4);
    transpose_w<<<gt, dim3(32, 8)>>>(Wq, Wk, Wv, Wo);

    dim3 g1(DD / 128, (BB * TT) / 128, 3);
    gemm_tc<0><<<g1, 256, GEMM_SMEM>>>(bq, bk, bv, nullptr);

    dim3 g2(TT / 128, BB * HH);
    attn_tc<<<g2, 128, 96 * 1024>>>();

    dim3 g3(DD / 128, (BB * TT) / 128);
    gemm_tc<1><<<g3, 256, GEMM_SMEM>>>(bo, nullptr, nullptr, out);
}